// round 12
// baseline (speedup 1.0000x reference)
#include <cuda_runtime.h>
#include <math.h>
#include <stdint.h>

// ---------------------------------------------------------------------------
// ShowAttendTellCore on GB300 (sm_103a).
// Round 10: tcgen05 is unusable (harness compiles via compute_103, ptxas
// rejects tcgen05 on .target sm_103). GEMM1 moves to portable-PTX tf32
// mma.sync (m16n8k8) on the tensor pipe, with the tanh/W_alpha scores
// reduction fused into the epilogue as additive per-N-tile partials.
//
// Inputs (metadata order):
//  0 xt[512,512] 1 fc_feats(unused) 2 att_feats[512,196,2048] 3 h[1,512,512]
//  4 c[1,512,512] 5 W_ctx[512,2048] 6 b_ctx[512] 7 W_h2att[512,512]
//  8 b_h2att[512] 9 W_alpha[1,512] 10 b_alpha[1] 11 W_ih[2048,2560]
// 12 W_hh[2048,512]
// Output: h_new[512,512] ++ h_new ++ c_new
// ---------------------------------------------------------------------------

#define BATCH   512
#define LSEQ    196
#define DATT    2048
#define HATT    512
#define DRNN    512
#define ROWS    (BATCH * LSEQ)      // 100352
#define NCT     4                   // N tiles of 128 over HATT=512

__device__ float g_atth[BATCH * HATT];
__device__ float g_part[NCT * ROWS];      // per-N-tile partial scores
__device__ float g_scores[ROWS];
__device__ float g_attres[BATCH * DATT];
__device__ float g_gates[BATCH * 4 * DRNN];

// ===================== tf32 mma.sync fused GEMM1 ===========================
// CTA tile 128(M) x 128(N), K = 2048 in 64 chunks of 32, double buffered.
// 8 warps: 4 (M) x 2 (N); warp tile 32(M) x 64(N) = 2x8 m16n8k8 mmas/kstep.
// smem rows padded to 36 floats -> conflict-free fragment LDS.

#define KC 32
#define NKCH (DATT / KC)           // 64
#define SMPAD 36

struct SmemGemm {
    float As[2][128][SMPAD];
    float Bs[2][128][SMPAD];
    float part[128][2];
};
#define SMEM_G (sizeof(SmemGemm))   // ~74.8 KB

__device__ __forceinline__ uint32_t smem_u32(const void* p) {
    uint32_t a;
    asm("{ .reg .u64 t; cvta.to.shared.u64 t, %1; cvt.u32.u64 %0, t; }"
        : "=r"(a) : "l"(p));
    return a;
}
__device__ __forceinline__ void cp16(uint32_t s, const void* g) {
    asm volatile("cp.async.cg.shared.global [%0], [%1], 16;" :: "r"(s), "l"(g));
}
__device__ __forceinline__ uint32_t f2tf32(float f) {
    uint32_t u;
    asm("cvt.rna.tf32.f32 %0, %1;" : "=r"(u) : "f"(f));
    return u;
}
__device__ __forceinline__ void mma_tf32(float* c, const uint32_t* a,
                                         const uint32_t* b) {
    asm volatile(
        "mma.sync.aligned.m16n8k8.row.col.f32.tf32.tf32.f32 "
        "{%0,%1,%2,%3}, {%4,%5,%6,%7}, {%8,%9}, {%0,%1,%2,%3};"
        : "+f"(c[0]), "+f"(c[1]), "+f"(c[2]), "+f"(c[3])
        : "r"(a[0]), "r"(a[1]), "r"(a[2]), "r"(a[3]), "r"(b[0]), "r"(b[1]));
}

__device__ __forceinline__ void fill_stage(SmemGemm* sm, int s,
                                           const float* __restrict__ Ab,
                                           const float* __restrict__ Bb,
                                           int k0, int tid)
{
    #pragma unroll
    for (int i = 0; i < 8; i++) {
        int idx = tid + i * 256;                // 0..2047
        int row = (idx >> 3) & 127;
        int q   = (idx & 7) * 4;
        if (idx < 1024)
            cp16(smem_u32(&sm->As[s][row][q]), Ab + (size_t)row * DATT + k0 + q);
        else
            cp16(smem_u32(&sm->Bs[s][row][q]), Bb + (size_t)row * DATT + k0 + q);
    }
    asm volatile("cp.async.commit_group;" ::: "memory");
}

// part[ctile][row] = sum_{h in ctile} wal[h] * tanh(att[row,h]+bctx[h]+atth[b,h])
__global__ void __launch_bounds__(256, 2)
att_scores_mma(const float* __restrict__ att_feats,
               const float* __restrict__ W_ctx,
               const float* __restrict__ atth,
               const float* __restrict__ W_alpha,
               const float* __restrict__ b_ctx,
               float* __restrict__ part)
{
    extern __shared__ char smem_raw[];
    SmemGemm* sm = (SmemGemm*)smem_raw;

    const int tid  = threadIdx.x;
    const int warp = tid >> 5;
    const int lane = tid & 31;
    const int g    = lane >> 2;        // group id 0..7
    const int t    = lane & 3;         // thread in group
    const int wm   = warp >> 1;        // 0..3 -> M
    const int wn   = warp & 1;         // 0..1 -> N
    const int m0   = wm * 32;
    const int n0   = wn * 64;

    const int ctile   = blockIdx.x;    // 0..3
    const int rowtile = blockIdx.y;    // 0..783
    const float* Ab = att_feats + (size_t)rowtile * 128 * DATT;
    const float* Bb = W_ctx     + (size_t)ctile   * 128 * DATT;

    float acc[2][8][4];
    #pragma unroll
    for (int mi = 0; mi < 2; mi++)
        #pragma unroll
        for (int ni = 0; ni < 8; ni++)
            #pragma unroll
            for (int r = 0; r < 4; r++) acc[mi][ni][r] = 0.f;

    fill_stage(sm, 0, Ab, Bb, 0, tid);

    for (int c = 0; c < NKCH; c++) {
        const int cur = c & 1;
        if (c + 1 < NKCH) {
            fill_stage(sm, cur ^ 1, Ab, Bb, (c + 1) * KC, tid);
            asm volatile("cp.async.wait_group 1;" ::: "memory");
        } else {
            asm volatile("cp.async.wait_group 0;" ::: "memory");
        }
        __syncthreads();

        #pragma unroll
        for (int ks = 0; ks < 4; ks++) {
            const int kk = ks * 8;
            uint32_t a[2][4];
            #pragma unroll
            for (int mi = 0; mi < 2; mi++) {
                const int mb = m0 + mi * 16;
                a[mi][0] = f2tf32(sm->As[cur][mb + g    ][kk + t    ]);
                a[mi][1] = f2tf32(sm->As[cur][mb + g + 8][kk + t    ]);
                a[mi][2] = f2tf32(sm->As[cur][mb + g    ][kk + t + 4]);
                a[mi][3] = f2tf32(sm->As[cur][mb + g + 8][kk + t + 4]);
            }
            #pragma unroll
            for (int ni = 0; ni < 8; ni++) {
                const int nb = n0 + ni * 8;
                uint32_t b[2];
                b[0] = f2tf32(sm->Bs[cur][nb + g][kk + t    ]);
                b[1] = f2tf32(sm->Bs[cur][nb + g][kk + t + 4]);
                mma_tf32(acc[0][ni], a[0], b);
                mma_tf32(acc[1][ni], a[1], b);
            }
        }
        __syncthreads();
    }

    // ---- fused epilogue: partial scores over this 128-col tile ----
    // thread rows: m0 + mi*16 + g (+8). psum idx = mi*2 + hi.
    float psum[4] = {0.f, 0.f, 0.f, 0.f};
    int   bidx[4];
    #pragma unroll
    for (int mi = 0; mi < 2; mi++) {
        int r0 = rowtile * 128 + m0 + mi * 16 + g;
        bidx[mi * 2 + 0] = r0 / LSEQ;
        bidx[mi * 2 + 1] = (r0 + 8) / LSEQ;
    }
    #pragma unroll
    for (int ni = 0; ni < 8; ni++) {
        const int h0 = ctile * 128 + n0 + ni * 8 + 2 * t;
        const float w0 = __ldg(W_alpha + h0),     w1 = __ldg(W_alpha + h0 + 1);
        const float bc0 = __ldg(b_ctx + h0),      bc1 = __ldg(b_ctx + h0 + 1);
        #pragma unroll
        for (int mi = 0; mi < 2; mi++) {
            const float* ahA = atth + (size_t)bidx[mi * 2 + 0] * HATT;
            const float* ahB = atth + (size_t)bidx[mi * 2 + 1] * HATT;
            psum[mi * 2 + 0] += w0 * tanhf(acc[mi][ni][0] + bc0 + __ldg(ahA + h0));
            psum[mi * 2 + 0] += w1 * tanhf(acc[mi][ni][1] + bc1 + __ldg(ahA + h0 + 1));
            psum[mi * 2 + 1] += w0 * tanhf(acc[mi][ni][2] + bc0 + __ldg(ahB + h0));
            psum[mi * 2 + 1] += w1 * tanhf(acc[mi][ni][3] + bc1 + __ldg(ahB + h0 + 1));
        }
    }
    // reduce across the 4 lanes of each group (t = 0..3)
    #pragma unroll
    for (int p = 0; p < 4; p++) {
        psum[p] += __shfl_xor_sync(0xffffffffu, psum[p], 1);
        psum[p] += __shfl_xor_sync(0xffffffffu, psum[p], 2);
    }
    if (t == 0) {
        #pragma unroll
        for (int mi = 0; mi < 2; mi++) {
            sm->part[m0 + mi * 16 + g    ][wn] = psum[mi * 2 + 0];
            sm->part[m0 + mi * 16 + g + 8][wn] = psum[mi * 2 + 1];
        }
    }
    __syncthreads();
    if (tid < 128) {
        part[(size_t)ctile * ROWS + rowtile * 128 + tid] =
            sm->part[tid][0] + sm->part[tid][1];
    }
}

// ======================= SIMT fp32 GEMM (small mats) =======================
#define BM 128
#define BN 128
#define BK 16

__global__ __launch_bounds__(256, 2)
void gemm_tn(int M, int N, int K,
             const float* __restrict__ A, int lda,
             const float* __restrict__ B, int ldb,
             float* __restrict__ C, int ldc,
             const float* __restrict__ bias, int accumulate)
{
    __shared__ float As[BK][BM];
    __shared__ float Bs[BK][BN];

    const int tid = threadIdx.x;
    const int tx  = tid & 15;
    const int ty  = tid >> 4;

    const float* Ab = A + (size_t)blockIdx.y * BM * lda;
    const float* Bb = B + (size_t)blockIdx.x * BN * ldb;

    float acc[8][8];
    #pragma unroll
    for (int i = 0; i < 8; i++)
        #pragma unroll
        for (int j = 0; j < 8; j++) acc[i][j] = 0.f;

    for (int k0 = 0; k0 < K; k0 += BK) {
        #pragma unroll
        for (int i = 0; i < 2; i++) {
            int idx = tid + i * 256;
            int row = idx >> 2;
            int q   = (idx & 3) << 2;
            float4 va = *(const float4*)(Ab + (size_t)row * lda + k0 + q);
            As[q + 0][row] = va.x; As[q + 1][row] = va.y;
            As[q + 2][row] = va.z; As[q + 3][row] = va.w;
            float4 vb = *(const float4*)(Bb + (size_t)row * ldb + k0 + q);
            Bs[q + 0][row] = vb.x; Bs[q + 1][row] = vb.y;
            Bs[q + 2][row] = vb.z; Bs[q + 3][row] = vb.w;
        }
        __syncthreads();

        #pragma unroll
        for (int k = 0; k < BK; k++) {
            float a[8], b[8];
            *(float4*)&a[0] = *(const float4*)&As[k][ty * 8];
            *(float4*)&a[4] = *(const float4*)&As[k][ty * 8 + 4];
            *(float4*)&b[0] = *(const float4*)&Bs[k][tx * 8];
            *(float4*)&b[4] = *(const float4*)&Bs[k][tx * 8 + 4];
            #pragma unroll
            for (int i = 0; i < 8; i++)
                #pragma unroll
                for (int j = 0; j < 8; j++)
                    acc[i][j] += a[i] * b[j];
        }
        __syncthreads();
    }

    const int row0 = blockIdx.y * BM + ty * 8;
    const int col0 = blockIdx.x * BN + tx * 8;
    #pragma unroll
    for (int i = 0; i < 8; i++) {
        float* Crow = C + (size_t)(row0 + i) * ldc + col0;
        if (accumulate) {
            #pragma unroll
            for (int j = 0; j < 8; j++) Crow[j] += acc[i][j];
        } else if (bias != nullptr) {
            #pragma unroll
            for (int j = 0; j < 8; j++) Crow[j] = acc[i][j] + bias[col0 + j];
        } else {
            #pragma unroll
            for (int j = 0; j < 8; j++) Crow[j] = acc[i][j];
        }
    }
}

// ================= softmax over L (fused partial-sum read) =================
// b_alpha omitted: softmax is shift-invariant.
__global__ void softmax_kernel(const float* __restrict__ part,
                               float* __restrict__ scores)
{
    __shared__ float red[8];
    int b = blockIdx.x;
    int t = threadIdx.x;

    float v = -1e30f;
    if (t < LSEQ) {
        size_t r = (size_t)b * LSEQ + t;
        v = part[r] + part[ROWS + r] + part[2 * (size_t)ROWS + r]
          + part[3 * (size_t)ROWS + r];
    }
    float m = v;
    #pragma unroll
    for (int o = 16; o; o >>= 1) m = fmaxf(m, __shfl_xor_sync(0xffffffffu, m, o));
    if ((t & 31) == 0) red[t >> 5] = m;
    __syncthreads();
    float bm = red[0];
    #pragma unroll
    for (int i = 1; i < 8; i++) bm = fmaxf(bm, red[i]);

    float e = (t < LSEQ) ? expf(v - bm) : 0.f;
    __syncthreads();
    float ss = e;
    #pragma unroll
    for (int o = 16; o; o >>= 1) ss += __shfl_xor_sync(0xffffffffu, ss, o);
    if ((t & 31) == 0) red[t >> 5] = ss;
    __syncthreads();
    float tot = 0.f;
    #pragma unroll
    for (int i = 0; i < 8; i++) tot += red[i];

    if (t < LSEQ) scores[(size_t)b * LSEQ + t] = e / tot;
}

// ==================== att_res = weights @ att_feats ========================
__global__ void attres_kernel(const float* __restrict__ att_feats,
                              const float* __restrict__ w,
                              float* __restrict__ out)
{
    __shared__ float ws[LSEQ];
    int b = blockIdx.x >> 3;
    int d = ((blockIdx.x & 7) << 8) + threadIdx.x;
    if (threadIdx.x < LSEQ) ws[threadIdx.x] = w[(size_t)b * LSEQ + threadIdx.x];
    __syncthreads();

    const float* base = att_feats + (size_t)b * LSEQ * DATT + d;
    float acc = 0.f;
    #pragma unroll 4
    for (int l = 0; l < LSEQ; l++)
        acc += ws[l] * base[(size_t)l * DATT];
    out[(size_t)b * DATT + d] = acc;
}

// ============================ LSTM elementwise =============================
__device__ __forceinline__ float sigf(float x) { return 1.f / (1.f + expf(-x)); }

__global__ void lstm_kernel(const float* __restrict__ gates,
                            const float* __restrict__ c_prev,
                            float* __restrict__ out, int out_size)
{
    int idx = blockIdx.x * blockDim.x + threadIdx.x;
    int b = idx >> 9;
    int j = idx & 511;
    const float* g = gates + (size_t)b * (4 * DRNN);
    float i_ = sigf(g[j]);
    float f_ = sigf(g[DRNN + j]);
    float gg = tanhf(g[2 * DRNN + j]);
    float o_ = sigf(g[3 * DRNN + j]);
    float cn = f_ * c_prev[idx] + i_ * gg;
    float hn = o_ * tanhf(cn);

    out[idx] = hn;
    if (out_size >= 2 * BATCH * DRNN) out[BATCH * DRNN + idx] = hn;
    if (out_size >= 3 * BATCH * DRNN) out[2 * BATCH * DRNN + idx] = cn;
}

// ---------------------------------------------------------------------------
extern "C" void kernel_launch(void* const* d_in, const int* in_sizes, int n_in,
                              void* d_out, int out_size)
{
    const float* xt        = (const float*)d_in[0];
    const float* att_feats = (const float*)d_in[2];
    const float* h         = (const float*)d_in[3];
    const float* c         = (const float*)d_in[4];
    const float* W_ctx     = (const float*)d_in[5];
    const float* b_ctx     = (const float*)d_in[6];
    const float* W_h2att   = (const float*)d_in[7];
    const float* b_h2att   = (const float*)d_in[8];
    const float* W_alpha   = (const float*)d_in[9];
    const float* W_ih      = (const float*)d_in[11];
    const float* W_hh      = (const float*)d_in[12];
    float* out = (float*)d_out;

    float *atth, *part, *scores, *attres, *gates;
    cudaGetSymbolAddress((void**)&atth,   g_atth);
    cudaGetSymbolAddress((void**)&part,   g_part);
    cudaGetSymbolAddress((void**)&scores, g_scores);
    cudaGetSymbolAddress((void**)&attres, g_attres);
    cudaGetSymbolAddress((void**)&gates,  g_gates);

    cudaFuncSetAttribute(att_scores_mma,
                         cudaFuncAttributeMaxDynamicSharedMemorySize, SMEM_G);

    // att_h = h_last @ W_h2att^T + b_h2att           [512,512]
    gemm_tn<<<dim3(HATT / BN, BATCH / BM), 256>>>(
        BATCH, HATT, DRNN, h, DRNN, W_h2att, DRNN, atth, HATT, b_h2att, 0);

    // fused GEMM1 (tf32 mma.sync) + tanh/W_alpha partial reductions
    att_scores_mma<<<dim3(NCT, ROWS / 128), 256, SMEM_G>>>(
        att_feats, W_ctx, atth, W_alpha, b_ctx, part);

    // softmax over L per batch row (sums the 4 partials)
    softmax_kernel<<<BATCH, 256>>>(part, scores);

    // att_res = weights @ att_feats                  [512,2048]
    attres_kernel<<<BATCH * (DATT / 256), 256>>>(att_feats, scores, attres);

    // gates = xt @ W_ih[:, :512]^T + att_res @ W_ih[:, 512:]^T + h @ W_hh^T
    gemm_tn<<<dim3(4 * DRNN / BN, BATCH / BM), 256>>>(
        BATCH, 4 * DRNN, DRNN, xt, DRNN, W_ih, DRNN + DATT, gates, 4 * DRNN,
        nullptr, 0);
    gemm_tn<<<dim3(4 * DRNN / BN, BATCH / BM), 256>>>(
        BATCH, 4 * DRNN, DATT, attres, DATT, W_ih + DRNN, DRNN + DATT, gates,
        4 * DRNN, nullptr, 1);
    gemm_tn<<<dim3(4 * DRNN / BN, BATCH / BM), 256>>>(
        BATCH, 4 * DRNN, DRNN, h, DRNN, W_hh, DRNN, gates, 4 * DRNN,
        nullptr, 1);

    // LSTM elementwise + output writes
    lstm_kernel<<<(BATCH * DRNN) / 256, 256>>>(gates, c, out, out_size);
}

// round 13
// speedup vs baseline: 1.2699x; 1.2699x over previous
#include <cuda_runtime.h>
#include <math.h>
#include <stdint.h>

// ---------------------------------------------------------------------------
// ShowAttendTellCore on GB300 (sm_103a).
// Round 13: GEMM1 gets a 3-stage cp.async ring + raw-bit tf32 fragments
// (no cvt); the three gates GEMMs fuse into one tf32 mma.sync kernel over
// concatenated K = [xt | attres | h] x [W_ih | W_hh].
// ---------------------------------------------------------------------------

#define BATCH   512
#define LSEQ    196
#define DATT    2048
#define HATT    512
#define DRNN    512
#define ROWS    (BATCH * LSEQ)      // 100352
#define NCT     4                   // N tiles of 128 over HATT=512

__device__ float g_atth[BATCH * HATT];
__device__ float g_part[NCT * ROWS];      // per-N-tile partial scores
__device__ float g_scores[ROWS];
__device__ float g_attres[BATCH * DATT];
__device__ float g_gates[BATCH * 4 * DRNN];

// ===================== tf32 mma.sync GEMM common ===========================
#define KC 32
#define NKCH (DATT / KC)           // 64  (GEMM1)
#define SMPAD 36
#define STAGES 3

struct SmemGemm {
    float As[STAGES][128][SMPAD];
    float Bs[STAGES][128][SMPAD];
    float part[128][2];
};
#define SMEM_G (sizeof(SmemGemm))   // ~111.6 KB

__device__ __forceinline__ uint32_t smem_u32(const void* p) {
    uint32_t a;
    asm("{ .reg .u64 t; cvta.to.shared.u64 t, %1; cvt.u32.u64 %0, t; }"
        : "=r"(a) : "l"(p));
    return a;
}
__device__ __forceinline__ void cp16(uint32_t s, const void* g) {
    asm volatile("cp.async.cg.shared.global [%0], [%1], 16;" :: "r"(s), "l"(g));
}
__device__ __forceinline__ void cp_commit() {
    asm volatile("cp.async.commit_group;" ::: "memory");
}
__device__ __forceinline__ void cp_wait2() {
    asm volatile("cp.async.wait_group 2;" ::: "memory");
}
// raw fp32 bits are valid tf32 operands (HW ignores low mantissa bits)
__device__ __forceinline__ void mma_tf32(float* c, const uint32_t* a,
                                         const uint32_t* b) {
    asm volatile(
        "mma.sync.aligned.m16n8k8.row.col.f32.tf32.tf32.f32 "
        "{%0,%1,%2,%3}, {%4,%5,%6,%7}, {%8,%9}, {%0,%1,%2,%3};"
        : "+f"(c[0]), "+f"(c[1]), "+f"(c[2]), "+f"(c[3])
        : "r"(a[0]), "r"(a[1]), "r"(a[2]), "r"(a[3]), "r"(b[0]), "r"(b[1]));
}

// Compute 4 k-steps of one chunk for one warp (shared by both gemm kernels).
__device__ __forceinline__ void mma_chunk(const SmemGemm* sm, int cur,
                                          int m0, int n0, int g, int t,
                                          float acc[2][8][4])
{
    #pragma unroll
    for (int ks = 0; ks < 4; ks++) {
        const int kk = ks * 8;
        uint32_t a[2][4];
        #pragma unroll
        for (int mi = 0; mi < 2; mi++) {
            const int mb = m0 + mi * 16;
            a[mi][0] = __float_as_uint(sm->As[cur][mb + g    ][kk + t    ]);
            a[mi][1] = __float_as_uint(sm->As[cur][mb + g + 8][kk + t    ]);
            a[mi][2] = __float_as_uint(sm->As[cur][mb + g    ][kk + t + 4]);
            a[mi][3] = __float_as_uint(sm->As[cur][mb + g + 8][kk + t + 4]);
        }
        #pragma unroll
        for (int ni = 0; ni < 8; ni++) {
            const int nb = n0 + ni * 8;
            uint32_t b[2];
            b[0] = __float_as_uint(sm->Bs[cur][nb + g][kk + t    ]);
            b[1] = __float_as_uint(sm->Bs[cur][nb + g][kk + t + 4]);
            mma_tf32(acc[0][ni], a[0], b);
            mma_tf32(acc[1][ni], a[1], b);
        }
    }
}

// ======================= GEMM1 + fused scores ==============================
__device__ __forceinline__ void fill_stage(SmemGemm* sm, int s,
                                           const float* __restrict__ Ab,
                                           const float* __restrict__ Bb,
                                           int k0, int tid)
{
    #pragma unroll
    for (int i = 0; i < 8; i++) {
        int idx = tid + i * 256;                // 0..2047
        int row = (idx >> 3) & 127;
        int q   = (idx & 7) * 4;
        if (idx < 1024)
            cp16(smem_u32(&sm->As[s][row][q]), Ab + (size_t)row * DATT + k0 + q);
        else
            cp16(smem_u32(&sm->Bs[s][row][q]), Bb + (size_t)row * DATT + k0 + q);
    }
    cp_commit();
}

// part[ctile][row] = sum_{h in ctile} wal[h]*tanh(att[row,h]+bctx[h]+atth[b,h])
__global__ void __launch_bounds__(256, 2)
att_scores_mma(const float* __restrict__ att_feats,
               const float* __restrict__ W_ctx,
               const float* __restrict__ atth,
               const float* __restrict__ W_alpha,
               const float* __restrict__ b_ctx,
               float* __restrict__ part)
{
    extern __shared__ char smem_raw[];
    SmemGemm* sm = (SmemGemm*)smem_raw;

    const int tid  = threadIdx.x;
    const int warp = tid >> 5;
    const int lane = tid & 31;
    const int g    = lane >> 2;
    const int t    = lane & 3;
    const int m0   = (warp >> 1) * 32;
    const int wn   = warp & 1;
    const int n0   = wn * 64;

    const int ctile   = blockIdx.x;    // 0..3
    const int rowtile = blockIdx.y;    // 0..783
    const float* Ab = att_feats + (size_t)rowtile * 128 * DATT;
    const float* Bb = W_ctx     + (size_t)ctile   * 128 * DATT;

    float acc[2][8][4];
    #pragma unroll
    for (int mi = 0; mi < 2; mi++)
        #pragma unroll
        for (int ni = 0; ni < 8; ni++)
            #pragma unroll
            for (int r = 0; r < 4; r++) acc[mi][ni][r] = 0.f;

    fill_stage(sm, 0, Ab, Bb, 0, tid);
    fill_stage(sm, 1, Ab, Bb, KC, tid);

    for (int c = 0; c < NKCH; c++) {
        const int cur = c % STAGES;
        const int pre = c + STAGES - 1;
        if (pre < NKCH)
            fill_stage(sm, pre % STAGES, Ab, Bb, pre * KC, tid);
        else
            cp_commit();                 // empty group keeps wait arithmetic
        cp_wait2();                      // oldest (chunk c) complete
        __syncthreads();
        mma_chunk(sm, cur, m0, n0, g, t, acc);
        __syncthreads();
    }

    // ---- fused epilogue: partial scores over this 128-col tile ----
    float psum[4] = {0.f, 0.f, 0.f, 0.f};
    int   bidx[4];
    #pragma unroll
    for (int mi = 0; mi < 2; mi++) {
        int r0 = rowtile * 128 + m0 + mi * 16 + g;
        bidx[mi * 2 + 0] = r0 / LSEQ;
        bidx[mi * 2 + 1] = (r0 + 8) / LSEQ;
    }
    #pragma unroll
    for (int ni = 0; ni < 8; ni++) {
        const int h0 = ctile * 128 + n0 + ni * 8 + 2 * t;
        const float w0 = __ldg(W_alpha + h0),  w1 = __ldg(W_alpha + h0 + 1);
        const float bc0 = __ldg(b_ctx + h0),   bc1 = __ldg(b_ctx + h0 + 1);
        #pragma unroll
        for (int mi = 0; mi < 2; mi++) {
            const float* ahA = atth + (size_t)bidx[mi * 2 + 0] * HATT;
            const float* ahB = atth + (size_t)bidx[mi * 2 + 1] * HATT;
            psum[mi * 2 + 0] += w0 * tanhf(acc[mi][ni][0] + bc0 + __ldg(ahA + h0));
            psum[mi * 2 + 0] += w1 * tanhf(acc[mi][ni][1] + bc1 + __ldg(ahA + h0 + 1));
            psum[mi * 2 + 1] += w0 * tanhf(acc[mi][ni][2] + bc0 + __ldg(ahB + h0));
            psum[mi * 2 + 1] += w1 * tanhf(acc[mi][ni][3] + bc1 + __ldg(ahB + h0 + 1));
        }
    }
    #pragma unroll
    for (int p = 0; p < 4; p++) {
        psum[p] += __shfl_xor_sync(0xffffffffu, psum[p], 1);
        psum[p] += __shfl_xor_sync(0xffffffffu, psum[p], 2);
    }
    if (t == 0) {
        #pragma unroll
        for (int mi = 0; mi < 2; mi++) {
            sm->part[m0 + mi * 16 + g    ][wn] = psum[mi * 2 + 0];
            sm->part[m0 + mi * 16 + g + 8][wn] = psum[mi * 2 + 1];
        }
    }
    __syncthreads();
    if (tid < 128) {
        part[(size_t)ctile * ROWS + rowtile * 128 + tid] =
            sm->part[tid][0] + sm->part[tid][1];
    }
}

// ================= fused gates GEMM (tf32 mma.sync) ========================
// gates[512, 2048] = [xt | attres | h](K=3072) @ [W_ih | W_hh]^T
// chunk c of 32: k0 = 32c. A src: c<16 -> xt, c<80 -> attres, else h.
//                           B src: c<80 -> W_ih, else W_hh.
#define KTOT_G 3072
#define NKCH_G (KTOT_G / KC)       // 96

__device__ __forceinline__ void fill_stage_g(SmemGemm* sm, int s, int k0,
                                             int rowtile, int ctile,
                                             const float* __restrict__ xt,
                                             const float* __restrict__ attres,
                                             const float* __restrict__ h,
                                             const float* __restrict__ W_ih,
                                             const float* __restrict__ W_hh,
                                             int tid)
{
    const float* asrc; int lda;
    if (k0 < 512)       { asrc = xt + k0;              lda = 512;  }
    else if (k0 < 2560) { asrc = attres + (k0 - 512);  lda = 2048; }
    else                { asrc = h + (k0 - 2560);      lda = 512;  }
    asrc += (size_t)rowtile * 128 * lda;

    const float* bsrc; int ldb;
    if (k0 < 2560) { bsrc = W_ih + k0;          ldb = 2560; }
    else           { bsrc = W_hh + (k0 - 2560); ldb = 512;  }
    bsrc += (size_t)ctile * 128 * ldb;

    #pragma unroll
    for (int i = 0; i < 8; i++) {
        int idx = tid + i * 256;
        int row = (idx >> 3) & 127;
        int q   = (idx & 7) * 4;
        if (idx < 1024)
            cp16(smem_u32(&sm->As[s][row][q]), asrc + (size_t)row * lda + q);
        else
            cp16(smem_u32(&sm->Bs[s][row][q]), bsrc + (size_t)row * ldb + q);
    }
    cp_commit();
}

__global__ void __launch_bounds__(256, 2)
gates_mma(const float* __restrict__ xt,
          const float* __restrict__ attres,
          const float* __restrict__ h,
          const float* __restrict__ W_ih,
          const float* __restrict__ W_hh,
          float* __restrict__ gates)
{
    extern __shared__ char smem_raw[];
    SmemGemm* sm = (SmemGemm*)smem_raw;

    const int tid  = threadIdx.x;
    const int warp = tid >> 5;
    const int lane = tid & 31;
    const int g    = lane >> 2;
    const int t    = lane & 3;
    const int m0   = (warp >> 1) * 32;
    const int n0   = (warp & 1) * 64;

    const int ctile   = blockIdx.x;    // 0..15
    const int rowtile = blockIdx.y;    // 0..3

    float acc[2][8][4];
    #pragma unroll
    for (int mi = 0; mi < 2; mi++)
        #pragma unroll
        for (int ni = 0; ni < 8; ni++)
            #pragma unroll
            for (int r = 0; r < 4; r++) acc[mi][ni][r] = 0.f;

    fill_stage_g(sm, 0, 0,  rowtile, ctile, xt, attres, h, W_ih, W_hh, tid);
    fill_stage_g(sm, 1, KC, rowtile, ctile, xt, attres, h, W_ih, W_hh, tid);

    for (int c = 0; c < NKCH_G; c++) {
        const int cur = c % STAGES;
        const int pre = c + STAGES - 1;
        if (pre < NKCH_G)
            fill_stage_g(sm, pre % STAGES, pre * KC, rowtile, ctile,
                         xt, attres, h, W_ih, W_hh, tid);
        else
            cp_commit();
        cp_wait2();
        __syncthreads();
        mma_chunk(sm, cur, m0, n0, g, t, acc);
        __syncthreads();
    }

    // store 128x128 tile
    const int grow = rowtile * 128 + m0;
    const int gcol = ctile * 128 + n0;
    #pragma unroll
    for (int mi = 0; mi < 2; mi++) {
        #pragma unroll
        for (int ni = 0; ni < 8; ni++) {
            int col = gcol + ni * 8 + 2 * t;
            float* p0 = gates + (size_t)(grow + mi * 16 + g)     * 2048 + col;
            float* p1 = gates + (size_t)(grow + mi * 16 + g + 8) * 2048 + col;
            p0[0] = acc[mi][ni][0]; p0[1] = acc[mi][ni][1];
            p1[0] = acc[mi][ni][2]; p1[1] = acc[mi][ni][3];
        }
    }
}

// ======================= SIMT fp32 GEMM (atth only) ========================
#define BM 128
#define BN 128
#define BK 16

__global__ __launch_bounds__(256, 2)
void gemm_tn(int M, int N, int K,
             const float* __restrict__ A, int lda,
             const float* __restrict__ B, int ldb,
             float* __restrict__ C, int ldc,
             const float* __restrict__ bias)
{
    __shared__ float As[BK][BM];
    __shared__ float Bs[BK][BN];

    const int tid = threadIdx.x;
    const int tx  = tid & 15;
    const int ty  = tid >> 4;

    const float* Ab = A + (size_t)blockIdx.y * BM * lda;
    const float* Bb = B + (size_t)blockIdx.x * BN * ldb;

    float acc[8][8];
    #pragma unroll
    for (int i = 0; i < 8; i++)
        #pragma unroll
        for (int j = 0; j < 8; j++) acc[i][j] = 0.f;

    for (int k0 = 0; k0 < K; k0 += BK) {
        #pragma unroll
        for (int i = 0; i < 2; i++) {
            int idx = tid + i * 256;
            int row = idx >> 2;
            int q   = (idx & 3) << 2;
            float4 va = *(const float4*)(Ab + (size_t)row * lda + k0 + q);
            As[q + 0][row] = va.x; As[q + 1][row] = va.y;
            As[q + 2][row] = va.z; As[q + 3][row] = va.w;
            float4 vb = *(const float4*)(Bb + (size_t)row * ldb + k0 + q);
            Bs[q + 0][row] = vb.x; Bs[q + 1][row] = vb.y;
            Bs[q + 2][row] = vb.z; Bs[q + 3][row] = vb.w;
        }
        __syncthreads();

        #pragma unroll
        for (int k = 0; k < BK; k++) {
            float a[8], b[8];
            *(float4*)&a[0] = *(const float4*)&As[k][ty * 8];
            *(float4*)&a[4] = *(const float4*)&As[k][ty * 8 + 4];
            *(float4*)&b[0] = *(const float4*)&Bs[k][tx * 8];
            *(float4*)&b[4] = *(const float4*)&Bs[k][tx * 8 + 4];
            #pragma unroll
            for (int i = 0; i < 8; i++)
                #pragma unroll
                for (int j = 0; j < 8; j++)
                    acc[i][j] += a[i] * b[j];
        }
        __syncthreads();
    }

    const int row0 = blockIdx.y * BM + ty * 8;
    const int col0 = blockIdx.x * BN + tx * 8;
    #pragma unroll
    for (int i = 0; i < 8; i++) {
        float* Crow = C + (size_t)(row0 + i) * ldc + col0;
        #pragma unroll
        for (int j = 0; j < 8; j++) Crow[j] = acc[i][j] + bias[col0 + j];
    }
}

// ================= softmax over L (fused partial-sum read) =================
__global__ void softmax_kernel(const float* __restrict__ part,
                               float* __restrict__ scores)
{
    __shared__ float red[8];
    int b = blockIdx.x;
    int t = threadIdx.x;

    float v = -1e30f;
    if (t < LSEQ) {
        size_t r = (size_t)b * LSEQ + t;
        v = part[r] + part[ROWS + r] + part[2 * (size_t)ROWS + r]
          + part[3 * (size_t)ROWS + r];
    }
    float m = v;
    #pragma unroll
    for (int o = 16; o; o >>= 1) m = fmaxf(m, __shfl_xor_sync(0xffffffffu, m, o));
    if ((t & 31) == 0) red[t >> 5] = m;
    __syncthreads();
    float bm = red[0];
    #pragma unroll
    for (int i = 1; i < 8; i++) bm = fmaxf(bm, red[i]);

    float e = (t < LSEQ) ? expf(v - bm) : 0.f;
    __syncthreads();
    float ss = e;
    #pragma unroll
    for (int o = 16; o; o >>= 1) ss += __shfl_xor_sync(0xffffffffu, ss, o);
    if ((t & 31) == 0) red[t >> 5] = ss;
    __syncthreads();
    float tot = 0.f;
    #pragma unroll
    for (int i = 0; i < 8; i++) tot += red[i];

    if (t < LSEQ) scores[(size_t)b * LSEQ + t] = e / tot;
}

// ==================== att_res = weights @ att_feats ========================
__global__ void attres_kernel(const float* __restrict__ att_feats,
                              const float* __restrict__ w,
                              float* __restrict__ out)
{
    __shared__ float ws[LSEQ];
    int b = blockIdx.x >> 3;
    int d = ((blockIdx.x & 7) << 8) + threadIdx.x;
    if (threadIdx.x < LSEQ) ws[threadIdx.x] = w[(size_t)b * LSEQ + threadIdx.x];
    __syncthreads();

    const float* base = att_feats + (size_t)b * LSEQ * DATT + d;
    float acc = 0.f;
    #pragma unroll 4
    for (int l = 0; l < LSEQ; l++)
        acc += ws[l] * base[(size_t)l * DATT];
    out[(size_t)b * DATT + d] = acc;
}

// ============================ LSTM elementwise =============================
__device__ __forceinline__ float sigf(float x) { return 1.f / (1.f + expf(-x)); }

__global__ void lstm_kernel(const float* __restrict__ gates,
                            const float* __restrict__ c_prev,
                            float* __restrict__ out, int out_size)
{
    int idx = blockIdx.x * blockDim.x + threadIdx.x;
    int b = idx >> 9;
    int j = idx & 511;
    const float* g = gates + (size_t)b * (4 * DRNN);
    float i_ = sigf(g[j]);
    float f_ = sigf(g[DRNN + j]);
    float gg = tanhf(g[2 * DRNN + j]);
    float o_ = sigf(g[3 * DRNN + j]);
    float cn = f_ * c_prev[idx] + i_ * gg;
    float hn = o_ * tanhf(cn);

    out[idx] = hn;
    if (out_size >= 2 * BATCH * DRNN) out[BATCH * DRNN + idx] = hn;
    if (out_size >= 3 * BATCH * DRNN) out[2 * BATCH * DRNN + idx] = cn;
}

// ---------------------------------------------------------------------------
extern "C" void kernel_launch(void* const* d_in, const int* in_sizes, int n_in,
                              void* d_out, int out_size)
{
    const float* xt        = (const float*)d_in[0];
    const float* att_feats = (const float*)d_in[2];
    const float* h         = (const float*)d_in[3];
    const float* c         = (const float*)d_in[4];
    const float* W_ctx     = (const float*)d_in[5];
    const float* b_ctx     = (const float*)d_in[6];
    const float* W_h2att   = (const float*)d_in[7];
    const float* b_h2att   = (const float*)d_in[8];
    const float* W_alpha   = (const float*)d_in[9];
    const float* W_ih      = (const float*)d_in[11];
    const float* W_hh      = (const float*)d_in[12];
    float* out = (float*)d_out;

    float *atth, *part, *scores, *attres, *gates;
    cudaGetSymbolAddress((void**)&atth,   g_atth);
    cudaGetSymbolAddress((void**)&part,   g_part);
    cudaGetSymbolAddress((void**)&scores, g_scores);
    cudaGetSymbolAddress((void**)&attres, g_attres);
    cudaGetSymbolAddress((void**)&gates,  g_gates);

    cudaFuncSetAttribute(att_scores_mma,
                         cudaFuncAttributeMaxDynamicSharedMemorySize, SMEM_G);
    cudaFuncSetAttribute(gates_mma,
                         cudaFuncAttributeMaxDynamicSharedMemorySize, SMEM_G);

    // att_h = h_last @ W_h2att^T + b_h2att           [512,512]
    gemm_tn<<<dim3(HATT / BN, BATCH / BM), 256>>>(
        BATCH, HATT, DRNN, h, DRNN, W_h2att, DRNN, atth, HATT, b_h2att);

    // fused GEMM1 (tf32 mma.sync, 3-stage pipeline) + scores partials
    att_scores_mma<<<dim3(NCT, ROWS / 128), 256, SMEM_G>>>(
        att_feats, W_ctx, atth, W_alpha, b_ctx, part);

    // softmax over L per batch row (sums the 4 partials)
    softmax_kernel<<<BATCH, 256>>>(part, scores);

    // att_res = weights @ att_feats                  [512,2048]
    attres_kernel<<<BATCH * (DATT / 256), 256>>>(att_feats, scores, attres);

    // fused gates GEMM: [xt|attres|h] @ [W_ih|W_hh]^T  (tf32 mma.sync)
    gates_mma<<<dim3(16, 4), 256, SMEM_G>>>(
        xt, attres, h, W_ih, W_hh, gates);

    // LSTM elementwise + output writes
    lstm_kernel<<<(BATCH * DRNN) / 256, 256>>>(gates, c, out, out_size);
}

// round 14
// speedup vs baseline: 1.3293x; 1.0468x over previous
#include <cuda_runtime.h>
#include <math.h>
#include <stdint.h>

// ---------------------------------------------------------------------------
// ShowAttendTellCore on GB300 (sm_103a).
// Round 14: single-barrier multistage mainloop (fill-before-mma) in both
// tf32 mma kernels; cvt.rna restored in the gates GEMM (output-precision
// path); attres vectorized to float4.
// ---------------------------------------------------------------------------

#define BATCH   512
#define LSEQ    196
#define DATT    2048
#define HATT    512
#define DRNN    512
#define ROWS    (BATCH * LSEQ)      // 100352
#define NCT     4                   // N tiles of 128 over HATT=512

__device__ float g_atth[BATCH * HATT];
__device__ float g_part[NCT * ROWS];      // per-N-tile partial scores
__device__ float g_scores[ROWS];
__device__ float g_attres[BATCH * DATT];
__device__ float g_gates[BATCH * 4 * DRNN];

// ===================== tf32 mma.sync GEMM common ===========================
#define KC 32
#define NKCH (DATT / KC)           // 64  (GEMM1)
#define SMPAD 36
#define STAGES 3

struct SmemGemm {
    float As[STAGES][128][SMPAD];
    float Bs[STAGES][128][SMPAD];
    float part[128][2];
};
#define SMEM_G (sizeof(SmemGemm))   // ~111.6 KB

__device__ __forceinline__ uint32_t smem_u32(const void* p) {
    uint32_t a;
    asm("{ .reg .u64 t; cvta.to.shared.u64 t, %1; cvt.u32.u64 %0, t; }"
        : "=r"(a) : "l"(p));
    return a;
}
__device__ __forceinline__ void cp16(uint32_t s, const void* g) {
    asm volatile("cp.async.cg.shared.global [%0], [%1], 16;" :: "r"(s), "l"(g));
}
__device__ __forceinline__ void cp_commit() {
    asm volatile("cp.async.commit_group;" ::: "memory");
}
__device__ __forceinline__ void cp_wait0() {
    asm volatile("cp.async.wait_group 0;" ::: "memory");
}
__device__ __forceinline__ void cp_wait1() {
    asm volatile("cp.async.wait_group 1;" ::: "memory");
}
__device__ __forceinline__ uint32_t f2tf32(float f) {
    uint32_t u;
    asm("cvt.rna.tf32.f32 %0, %1;" : "=r"(u) : "f"(f));
    return u;
}
__device__ __forceinline__ void mma_tf32(float* c, const uint32_t* a,
                                         const uint32_t* b) {
    asm volatile(
        "mma.sync.aligned.m16n8k8.row.col.f32.tf32.tf32.f32 "
        "{%0,%1,%2,%3}, {%4,%5,%6,%7}, {%8,%9}, {%0,%1,%2,%3};"
        : "+f"(c[0]), "+f"(c[1]), "+f"(c[2]), "+f"(c[3])
        : "r"(a[0]), "r"(a[1]), "r"(a[2]), "r"(a[3]), "r"(b[0]), "r"(b[1]));
}

// Compute 4 k-steps of one chunk for one warp.
// RNA=true rounds fragments to tf32 (output-precision path); false uses the
// raw fp32 bits (HW ignores low mantissa bits; ~2x error, zero ALU cost).
template <bool RNA>
__device__ __forceinline__ void mma_chunk(const SmemGemm* sm, int cur,
                                          int m0, int n0, int g, int t,
                                          float acc[2][8][4])
{
    #pragma unroll
    for (int ks = 0; ks < 4; ks++) {
        const int kk = ks * 8;
        uint32_t a[2][4];
        #pragma unroll
        for (int mi = 0; mi < 2; mi++) {
            const int mb = m0 + mi * 16;
            float a0 = sm->As[cur][mb + g    ][kk + t    ];
            float a1 = sm->As[cur][mb + g + 8][kk + t    ];
            float a2 = sm->As[cur][mb + g    ][kk + t + 4];
            float a3 = sm->As[cur][mb + g + 8][kk + t + 4];
            a[mi][0] = RNA ? f2tf32(a0) : __float_as_uint(a0);
            a[mi][1] = RNA ? f2tf32(a1) : __float_as_uint(a1);
            a[mi][2] = RNA ? f2tf32(a2) : __float_as_uint(a2);
            a[mi][3] = RNA ? f2tf32(a3) : __float_as_uint(a3);
        }
        #pragma unroll
        for (int ni = 0; ni < 8; ni++) {
            const int nb = n0 + ni * 8;
            uint32_t b[2];
            float b0 = sm->Bs[cur][nb + g][kk + t    ];
            float b1 = sm->Bs[cur][nb + g][kk + t + 4];
            b[0] = RNA ? f2tf32(b0) : __float_as_uint(b0);
            b[1] = RNA ? f2tf32(b1) : __float_as_uint(b1);
            mma_tf32(acc[0][ni], a[0], b);
            mma_tf32(acc[1][ni], a[1], b);
        }
    }
}

// ======================= GEMM1 + fused scores ==============================
__device__ __forceinline__ void fill_stage(SmemGemm* sm, int s,
                                           const float* __restrict__ Ab,
                                           const float* __restrict__ Bb,
                                           int k0, int tid)
{
    #pragma unroll
    for (int i = 0; i < 8; i++) {
        int idx = tid + i * 256;                // 0..2047
        int row = (idx >> 3) & 127;
        int q   = (idx & 7) * 4;
        if (idx < 1024)
            cp16(smem_u32(&sm->As[s][row][q]), Ab + (size_t)row * DATT + k0 + q);
        else
            cp16(smem_u32(&sm->Bs[s][row][q]), Bb + (size_t)row * DATT + k0 + q);
    }
    cp_commit();
}

// part[ctile][row] = sum_{h in ctile} wal[h]*tanh(att[row,h]+bctx[h]+atth[b,h])
__global__ void __launch_bounds__(256, 2)
att_scores_mma(const float* __restrict__ att_feats,
               const float* __restrict__ W_ctx,
               const float* __restrict__ atth,
               const float* __restrict__ W_alpha,
               const float* __restrict__ b_ctx,
               float* __restrict__ part)
{
    extern __shared__ char smem_raw[];
    SmemGemm* sm = (SmemGemm*)smem_raw;

    const int tid  = threadIdx.x;
    const int warp = tid >> 5;
    const int lane = tid & 31;
    const int g    = lane >> 2;
    const int t    = lane & 3;
    const int m0   = (warp >> 1) * 32;
    const int wn   = warp & 1;
    const int n0   = wn * 64;

    const int ctile   = blockIdx.x;    // 0..3
    const int rowtile = blockIdx.y;    // 0..783
    const float* Ab = att_feats + (size_t)rowtile * 128 * DATT;
    const float* Bb = W_ctx     + (size_t)ctile   * 128 * DATT;

    float acc[2][8][4];
    #pragma unroll
    for (int mi = 0; mi < 2; mi++)
        #pragma unroll
        for (int ni = 0; ni < 8; ni++)
            #pragma unroll
            for (int r = 0; r < 4; r++) acc[mi][ni][r] = 0.f;

    fill_stage(sm, 0, Ab, Bb, 0, tid);
    fill_stage(sm, 1, Ab, Bb, KC, tid);

    // Single-barrier multistage mainloop.
    // Invariant entering iter c: pending cp groups = {c, c+1} (clipped).
    // Barrier at iter c guarantees all warps consumed stage (c-1)%3, so the
    // fill for chunk c+2 -> stage (c+2)%3 == (c-1)%3 is safe and its DRAM
    // time hides under this chunk's mma.
    for (int c = 0; c < NKCH; c++) {
        if (c + 1 < NKCH) cp_wait1(); else cp_wait0();
        __syncthreads();
        if (c + 2 < NKCH)
            fill_stage(sm, (c + 2) % STAGES, Ab, Bb, (c + 2) * KC, tid);
        mma_chunk<false>(sm, c % STAGES, m0, n0, g, t, acc);
    }

    // ---- fused epilogue: partial scores over this 128-col tile ----
    float psum[4] = {0.f, 0.f, 0.f, 0.f};
    int   bidx[4];
    #pragma unroll
    for (int mi = 0; mi < 2; mi++) {
        int r0 = rowtile * 128 + m0 + mi * 16 + g;
        bidx[mi * 2 + 0] = r0 / LSEQ;
        bidx[mi * 2 + 1] = (r0 + 8) / LSEQ;
    }
    #pragma unroll
    for (int ni = 0; ni < 8; ni++) {
        const int h0 = ctile * 128 + n0 + ni * 8 + 2 * t;
        const float w0 = __ldg(W_alpha + h0),  w1 = __ldg(W_alpha + h0 + 1);
        const float bc0 = __ldg(b_ctx + h0),   bc1 = __ldg(b_ctx + h0 + 1);
        #pragma unroll
        for (int mi = 0; mi < 2; mi++) {
            const float* ahA = atth + (size_t)bidx[mi * 2 + 0] * HATT;
            const float* ahB = atth + (size_t)bidx[mi * 2 + 1] * HATT;
            psum[mi * 2 + 0] += w0 * tanhf(acc[mi][ni][0] + bc0 + __ldg(ahA + h0));
            psum[mi * 2 + 0] += w1 * tanhf(acc[mi][ni][1] + bc1 + __ldg(ahA + h0 + 1));
            psum[mi * 2 + 1] += w0 * tanhf(acc[mi][ni][2] + bc0 + __ldg(ahB + h0));
            psum[mi * 2 + 1] += w1 * tanhf(acc[mi][ni][3] + bc1 + __ldg(ahB + h0 + 1));
        }
    }
    #pragma unroll
    for (int p = 0; p < 4; p++) {
        psum[p] += __shfl_xor_sync(0xffffffffu, psum[p], 1);
        psum[p] += __shfl_xor_sync(0xffffffffu, psum[p], 2);
    }
    __syncthreads();   // mainloop smem no longer needed; reuse for part
    if (t == 0) {
        #pragma unroll
        for (int mi = 0; mi < 2; mi++) {
            sm->part[m0 + mi * 16 + g    ][wn] = psum[mi * 2 + 0];
            sm->part[m0 + mi * 16 + g + 8][wn] = psum[mi * 2 + 1];
        }
    }
    __syncthreads();
    if (tid < 128) {
        part[(size_t)ctile * ROWS + rowtile * 128 + tid] =
            sm->part[tid][0] + sm->part[tid][1];
    }
}

// ================= fused gates GEMM (tf32 mma.sync) ========================
// gates[512, 2048] = [xt | attres | h](K=3072) @ [W_ih | W_hh]^T
#define KTOT_G 3072
#define NKCH_G (KTOT_G / KC)       // 96

__device__ __forceinline__ void fill_stage_g(SmemGemm* sm, int s, int k0,
                                             int rowtile, int ctile,
                                             const float* __restrict__ xt,
                                             const float* __restrict__ attres,
                                             const float* __restrict__ h,
                                             const float* __restrict__ W_ih,
                                             const float* __restrict__ W_hh,
                                             int tid)
{
    const float* asrc; int lda;
    if (k0 < 512)       { asrc = xt + k0;              lda = 512;  }
    else if (k0 < 2560) { asrc = attres + (k0 - 512);  lda = 2048; }
    else                { asrc = h + (k0 - 2560);      lda = 512;  }
    asrc += (size_t)rowtile * 128 * lda;

    const float* bsrc; int ldb;
    if (k0 < 2560) { bsrc = W_ih + k0;          ldb = 2560; }
    else           { bsrc = W_hh + (k0 - 2560); ldb = 512;  }
    bsrc += (size_t)ctile * 128 * ldb;

    #pragma unroll
    for (int i = 0; i < 8; i++) {
        int idx = tid + i * 256;
        int row = (idx >> 3) & 127;
        int q   = (idx & 7) * 4;
        if (idx < 1024)
            cp16(smem_u32(&sm->As[s][row][q]), asrc + (size_t)row * lda + q);
        else
            cp16(smem_u32(&sm->Bs[s][row][q]), bsrc + (size_t)row * ldb + q);
    }
    cp_commit();
}

__global__ void __launch_bounds__(256, 2)
gates_mma(const float* __restrict__ xt,
          const float* __restrict__ attres,
          const float* __restrict__ h,
          const float* __restrict__ W_ih,
          const float* __restrict__ W_hh,
          float* __restrict__ gates)
{
    extern __shared__ char smem_raw[];
    SmemGemm* sm = (SmemGemm*)smem_raw;

    const int tid  = threadIdx.x;
    const int warp = tid >> 5;
    const int lane = tid & 31;
    const int g    = lane >> 2;
    const int t    = lane & 3;
    const int m0   = (warp >> 1) * 32;
    const int n0   = (warp & 1) * 64;

    const int ctile   = blockIdx.x;    // 0..15
    const int rowtile = blockIdx.y;    // 0..3

    float acc[2][8][4];
    #pragma unroll
    for (int mi = 0; mi < 2; mi++)
        #pragma unroll
        for (int ni = 0; ni < 8; ni++)
            #pragma unroll
            for (int r = 0; r < 4; r++) acc[mi][ni][r] = 0.f;

    fill_stage_g(sm, 0, 0,  rowtile, ctile, xt, attres, h, W_ih, W_hh, tid);
    fill_stage_g(sm, 1, KC, rowtile, ctile, xt, attres, h, W_ih, W_hh, tid);

    for (int c = 0; c < NKCH_G; c++) {
        if (c + 1 < NKCH_G) cp_wait1(); else cp_wait0();
        __syncthreads();
        if (c + 2 < NKCH_G)
            fill_stage_g(sm, (c + 2) % STAGES, (c + 2) * KC, rowtile, ctile,
                         xt, attres, h, W_ih, W_hh, tid);
        mma_chunk<true>(sm, c % STAGES, m0, n0, g, t, acc);  // rna: output path
    }

    // store 128x128 tile
    const int grow = rowtile * 128 + m0;
    const int gcol = ctile * 128 + n0;
    #pragma unroll
    for (int mi = 0; mi < 2; mi++) {
        #pragma unroll
        for (int ni = 0; ni < 8; ni++) {
            int col = gcol + ni * 8 + 2 * t;
            float* p0 = gates + (size_t)(grow + mi * 16 + g)     * 2048 + col;
            float* p1 = gates + (size_t)(grow + mi * 16 + g + 8) * 2048 + col;
            p0[0] = acc[mi][ni][0]; p0[1] = acc[mi][ni][1];
            p1[0] = acc[mi][ni][2]; p1[1] = acc[mi][ni][3];
        }
    }
}

// ======================= SIMT fp32 GEMM (atth only) ========================
#define BM 128
#define BN 128
#define BK 16

__global__ __launch_bounds__(256, 2)
void gemm_tn(int M, int N, int K,
             const float* __restrict__ A, int lda,
             const float* __restrict__ B, int ldb,
             float* __restrict__ C, int ldc,
             const float* __restrict__ bias)
{
    __shared__ float As[BK][BM];
    __shared__ float Bs[BK][BN];

    const int tid = threadIdx.x;
    const int tx  = tid & 15;
    const int ty  = tid >> 4;

    const float* Ab = A + (size_t)blockIdx.y * BM * lda;
    const float* Bb = B + (size_t)blockIdx.x * BN * ldb;

    float acc[8][8];
    #pragma unroll
    for (int i = 0; i < 8; i++)
        #pragma unroll
        for (int j = 0; j < 8; j++) acc[i][j] = 0.f;

    for (int k0 = 0; k0 < K; k0 += BK) {
        #pragma unroll
        for (int i = 0; i < 2; i++) {
            int idx = tid + i * 256;
            int row = idx >> 2;
            int q   = (idx & 3) << 2;
            float4 va = *(const float4*)(Ab + (size_t)row * lda + k0 + q);
            As[q + 0][row] = va.x; As[q + 1][row] = va.y;
            As[q + 2][row] = va.z; As[q + 3][row] = va.w;
            float4 vb = *(const float4*)(Bb + (size_t)row * ldb + k0 + q);
            Bs[q + 0][row] = vb.x; Bs[q + 1][row] = vb.y;
            Bs[q + 2][row] = vb.z; Bs[q + 3][row] = vb.w;
        }
        __syncthreads();

        #pragma unroll
        for (int k = 0; k < BK; k++) {
            float a[8], b[8];
            *(float4*)&a[0] = *(const float4*)&As[k][ty * 8];
            *(float4*)&a[4] = *(const float4*)&As[k][ty * 8 + 4];
            *(float4*)&b[0] = *(const float4*)&Bs[k][tx * 8];
            *(float4*)&b[4] = *(const float4*)&Bs[k][tx * 8 + 4];
            #pragma unroll
            for (int i = 0; i < 8; i++)
                #pragma unroll
                for (int j = 0; j < 8; j++)
                    acc[i][j] += a[i] * b[j];
        }
        __syncthreads();
    }

    const int row0 = blockIdx.y * BM + ty * 8;
    const int col0 = blockIdx.x * BN + tx * 8;
    #pragma unroll
    for (int i = 0; i < 8; i++) {
        float* Crow = C + (size_t)(row0 + i) * ldc + col0;
        #pragma unroll
        for (int j = 0; j < 8; j++) Crow[j] = acc[i][j] + bias[col0 + j];
    }
}

// ================= softmax over L (fused partial-sum read) =================
__global__ void softmax_kernel(const float* __restrict__ part,
                               float* __restrict__ scores)
{
    __shared__ float red[8];
    int b = blockIdx.x;
    int t = threadIdx.x;

    float v = -1e30f;
    if (t < LSEQ) {
        size_t r = (size_t)b * LSEQ + t;
        v = part[r] + part[ROWS + r] + part[2 * (size_t)ROWS + r]
          + part[3 * (size_t)ROWS + r];
    }
    float m = v;
    #pragma unroll
    for (int o = 16; o; o >>= 1) m = fmaxf(m, __shfl_xor_sync(0xffffffffu, m, o));
    if ((t & 31) == 0) red[t >> 5] = m;
    __syncthreads();
    float bm = red[0];
    #pragma unroll
    for (int i = 1; i < 8; i++) bm = fmaxf(bm, red[i]);

    float e = (t < LSEQ) ? expf(v - bm) : 0.f;
    __syncthreads();
    float ss = e;
    #pragma unroll
    for (int o = 16; o; o >>= 1) ss += __shfl_xor_sync(0xffffffffu, ss, o);
    if ((t & 31) == 0) red[t >> 5] = ss;
    __syncthreads();
    float tot = 0.f;
    #pragma unroll
    for (int i = 0; i < 8; i++) tot += red[i];

    if (t < LSEQ) scores[(size_t)b * LSEQ + t] = e / tot;
}

// ==================== att_res = weights @ att_feats ========================
// float4 per thread: block covers 1024 cols, 2 blocks per batch row.
__global__ void attres_kernel(const float* __restrict__ att_feats,
                              const float* __restrict__ w,
                              float* __restrict__ out)
{
    __shared__ float ws[LSEQ];
    int b  = blockIdx.x >> 1;
    int d4 = ((blockIdx.x & 1) << 8) + threadIdx.x;   // float4 index 0..511
    if (threadIdx.x < LSEQ) ws[threadIdx.x] = w[(size_t)b * LSEQ + threadIdx.x];
    __syncthreads();

    const float4* base = (const float4*)(att_feats + (size_t)b * LSEQ * DATT) + d4;
    float4 acc = make_float4(0.f, 0.f, 0.f, 0.f);
    #pragma unroll 4
    for (int l = 0; l < LSEQ; l++) {
        float4 v = base[(size_t)l * (DATT / 4)];
        float  s = ws[l];
        acc.x += s * v.x; acc.y += s * v.y;
        acc.z += s * v.z; acc.w += s * v.w;
    }
    ((float4*)(out + (size_t)b * DATT))[d4] = acc;
}

// ============================ LSTM elementwise =============================
__device__ __forceinline__ float sigf(float x) { return 1.f / (1.f + expf(-x)); }

__global__ void lstm_kernel(const float* __restrict__ gates,
                            const float* __restrict__ c_prev,
                            float* __restrict__ out, int out_size)
{
    int idx = blockIdx.x * blockDim.x + threadIdx.x;
    int b = idx >> 9;
    int j = idx & 511;
    const float* g = gates + (size_t)b * (4 * DRNN);
    float i_ = sigf(g[j]);
    float f_ = sigf(g[DRNN + j]);
    float gg = tanhf(g[2 * DRNN + j]);
    float o_ = sigf(g[3 * DRNN + j]);
    float cn = f_ * c_prev[idx] + i_ * gg;
    float hn = o_ * tanhf(cn);

    out[idx] = hn;
    if (out_size >= 2 * BATCH * DRNN) out[BATCH * DRNN + idx] = hn;
    if (out_size >= 3 * BATCH * DRNN) out[2 * BATCH * DRNN + idx] = cn;
}

// ---------------------------------------------------------------------------
extern "C" void kernel_launch(void* const* d_in, const int* in_sizes, int n_in,
                              void* d_out, int out_size)
{
    const float* xt        = (const float*)d_in[0];
    const float* att_feats = (const float*)d_in[2];
    const float* h         = (const float*)d_in[3];
    const float* c         = (const float*)d_in[4];
    const float* W_ctx     = (const float*)d_in[5];
    const float* b_ctx     = (const float*)d_in[6];
    const float* W_h2att   = (const float*)d_in[7];
    const float* b_h2att   = (const float*)d_in[8];
    const float* W_alpha   = (const float*)d_in[9];
    const float* W_ih      = (const float*)d_in[11];
    const float* W_hh      = (const float*)d_in[12];
    float* out = (float*)d_out;

    float *atth, *part, *scores, *attres, *gates;
    cudaGetSymbolAddress((void**)&atth,   g_atth);
    cudaGetSymbolAddress((void**)&part,   g_part);
    cudaGetSymbolAddress((void**)&scores, g_scores);
    cudaGetSymbolAddress((void**)&attres, g_attres);
    cudaGetSymbolAddress((void**)&gates,  g_gates);

    cudaFuncSetAttribute(att_scores_mma,
                         cudaFuncAttributeMaxDynamicSharedMemorySize, SMEM_G);
    cudaFuncSetAttribute(gates_mma,
                         cudaFuncAttributeMaxDynamicSharedMemorySize, SMEM_G);

    // att_h = h_last @ W_h2att^T + b_h2att           [512,512]
    gemm_tn<<<dim3(HATT / BN, BATCH / BM), 256>>>(
        BATCH, HATT, DRNN, h, DRNN, W_h2att, DRNN, atth, HATT, b_h2att);

    // fused GEMM1 (tf32 mma.sync, single-barrier multistage) + scores partials
    att_scores_mma<<<dim3(NCT, ROWS / 128), 256, SMEM_G>>>(
        att_feats, W_ctx, atth, W_alpha, b_ctx, part);

    // softmax over L per batch row (sums the 4 partials)
    softmax_kernel<<<BATCH, 256>>>(part, scores);

    // att_res = weights @ att_feats                  [512,2048]
    attres_kernel<<<BATCH * 2, 256>>>(att_feats, scores, attres);

    // fused gates GEMM: [xt|attres|h] @ [W_ih|W_hh]^T  (tf32 mma.sync, rna)
    gates_mma<<<dim3(16, 4), 256, SMEM_G>>>(
        xt, attres, h, W_ih, W_hh, gates);

    // LSTM elementwise + output writes
    lstm_kernel<<<(BATCH * DRNN) / 256, 256>>>(gates, c, out, out_size);
}